// round 2
// baseline (speedup 1.0000x reference)
#include <cuda_runtime.h>

#define NN 50000
#define NE 800000
#define NF 500
#define NH 256
#define NC 10
#define HID2 512   // both networks' hidden concatenated

// ---------------- scratch (device globals; no runtime allocation) -----------
__device__ __align__(256) float g_H0[NN * HID2];   // x@W1 + b1 (both nets)  102.4 MB
__device__ __align__(256) float g_H1[NN * HID2];   // relu(spmm(H0))          102.4 MB
__device__ __align__(256) float g_H2[NN * 2 * NC]; // H1@W2 + b2 (both nets)    4.0 MB
__device__ int   g_rowptr[NN + 1];
__device__ int   g_cnt[NN];
__device__ int   g_fill[NN];
__device__ int   g_cols[NE];
__device__ float g_w[NE];
__device__ int   g_is64;   // 1 if edge_index is int64, 0 if int32

// ---------------- dtype detect + CSR build ----------------------------------
__global__ void zero_kernel() {
    int i = blockIdx.x * blockDim.x + threadIdx.x;
    if (i < NN) { g_cnt[i] = 0; g_fill[i] = 0; }
    if (i == 0) g_is64 = 1;
}

// Read first NE elements as int64 (6.4 MB — never exceeds even an int32-sized
// buffer of 2*NE*4 = 6.4 MB). If edge_index is really int32, fused pairs are
// >= 2^32 almost surely -> flag flips to 0.
__global__ void detect_kernel(const long long* __restrict__ ei) {
    int e = blockIdx.x * blockDim.x + threadIdx.x;
    if (e < NE) {
        long long v = ei[e];
        if (v < 0 || v >= NN) atomicAnd(&g_is64, 0);
    }
}

__device__ __forceinline__ int edge_row(const void* ei, int e) {
    return g_is64 ? (int)((const long long*)ei)[e] : ((const int*)ei)[e];
}
__device__ __forceinline__ int edge_col(const void* ei, int e) {
    return g_is64 ? (int)((const long long*)ei)[NE + e] : ((const int*)ei)[NE + e];
}

__global__ void count_kernel(const void* __restrict__ ei) {
    int e = blockIdx.x * blockDim.x + threadIdx.x;
    if (e < NE) atomicAdd(&g_cnt[edge_row(ei, e)], 1);
}

// single-block exclusive scan of g_cnt -> g_rowptr (1024 threads, chunk 49)
__global__ void scan_kernel() {
    __shared__ int sums[1024];
    int t = threadIdx.x;
    const int CH = 49;  // 1024*49 = 50176 >= NN
    int s0 = t * CH;
    int s1 = s0 + CH; if (s1 > NN) s1 = NN;
    int s = 0;
    for (int i = s0; i < s1; i++) s += g_cnt[i];
    sums[t] = s;
    __syncthreads();
    for (int off = 1; off < 1024; off <<= 1) {
        int v = (t >= off) ? sums[t - off] : 0;
        __syncthreads();
        sums[t] += v;
        __syncthreads();
    }
    int base = (t == 0) ? 0 : sums[t - 1];
    for (int i = s0; i < s1; i++) { g_rowptr[i] = base; base += g_cnt[i]; }
    if (t == 1023) g_rowptr[NN] = sums[1023];
}

__global__ void scatter_kernel(const void* __restrict__ ei,
                               const float* __restrict__ ew) {
    int e = blockIdx.x * blockDim.x + threadIdx.x;
    if (e < NE) {
        int r = edge_row(ei, e);
        int c = edge_col(ei, e);
        int pos = g_rowptr[r] + atomicAdd(&g_fill[r], 1);
        g_cols[pos] = c;
        g_w[pos]    = ew[e];
    }
}

// ---------------- GEMM1: H0 = x @ [W1_1 | W1_2] + [b1_1 | b1_2] --------------
// 128x128 tile, BK=8, 256 threads, 8x8 microtile.
__global__ __launch_bounds__(256)
void gemm1_kernel(const float* __restrict__ x,
                  const float* __restrict__ Wa, const float* __restrict__ ba,
                  const float* __restrict__ Wb, const float* __restrict__ bb) {
    __shared__ __align__(16) float As[8][128];
    __shared__ __align__(16) float Bs[8][128];

    int tid   = threadIdx.x;
    int nbase = blockIdx.x * 128;          // 0,128,256,384
    int mbase = blockIdx.y * 128;

    const float* W    = (nbase >= NH) ? Wb : Wa;
    const float* bvec = (nbase >= NH) ? bb : ba;
    int ncol0 = nbase & (NH - 1);          // column offset inside one net's W

    int tx = tid & 15, ty = tid >> 4;

    float acc[8][8];
#pragma unroll
    for (int i = 0; i < 8; i++)
#pragma unroll
        for (int j = 0; j < 8; j++) acc[i][j] = 0.f;

    int arow = tid >> 1, ak = (tid & 1) * 4;    // A: 128 rows x 8 k
    int brow = tid >> 5, bn4 = (tid & 31) * 4;  // B: 8 k x 128 n
    int grow = mbase + arow;

    const int KT = (NF + 7) / 8;  // 63
    for (int kt = 0; kt < KT; kt++) {
        int k = kt * 8 + ak;
        float4 av = make_float4(0.f, 0.f, 0.f, 0.f);
        if (grow < NN && k + 3 < NF)
            av = *(const float4*)(x + (size_t)grow * NF + k);
        else if (grow < NN) {
            if (k + 0 < NF) av.x = x[(size_t)grow * NF + k + 0];
            if (k + 1 < NF) av.y = x[(size_t)grow * NF + k + 1];
            if (k + 2 < NF) av.z = x[(size_t)grow * NF + k + 2];
            if (k + 3 < NF) av.w = x[(size_t)grow * NF + k + 3];
        }
        As[ak + 0][arow] = av.x;
        As[ak + 1][arow] = av.y;
        As[ak + 2][arow] = av.z;
        As[ak + 3][arow] = av.w;

        int kb = kt * 8 + brow;
        float4 bv = make_float4(0.f, 0.f, 0.f, 0.f);
        if (kb < NF)
            bv = *(const float4*)(W + (size_t)kb * NH + ncol0 + bn4);
        *(float4*)&Bs[brow][bn4] = bv;

        __syncthreads();

#pragma unroll
        for (int kk = 0; kk < 8; kk++) {
            float a[8], b[8];
            *(float4*)(a)     = *(const float4*)&As[kk][ty * 8];
            *(float4*)(a + 4) = *(const float4*)&As[kk][ty * 8 + 4];
            *(float4*)(b)     = *(const float4*)&Bs[kk][tx * 8];
            *(float4*)(b + 4) = *(const float4*)&Bs[kk][tx * 8 + 4];
#pragma unroll
            for (int i = 0; i < 8; i++)
#pragma unroll
                for (int j = 0; j < 8; j++) acc[i][j] += a[i] * b[j];
        }
        __syncthreads();
    }

    float bias[8];
#pragma unroll
    for (int j = 0; j < 8; j++) bias[j] = bvec[ncol0 + tx * 8 + j];

#pragma unroll
    for (int i = 0; i < 8; i++) {
        int row = mbase + ty * 8 + i;
        if (row < NN) {
            float* dst = g_H0 + (size_t)row * HID2 + nbase + tx * 8;
            float4 v0 = make_float4(acc[i][0] + bias[0], acc[i][1] + bias[1],
                                    acc[i][2] + bias[2], acc[i][3] + bias[3]);
            float4 v1 = make_float4(acc[i][4] + bias[4], acc[i][5] + bias[5],
                                    acc[i][6] + bias[6], acc[i][7] + bias[7]);
            *(float4*)(dst)     = v0;
            *(float4*)(dst + 4) = v1;
        }
    }
}

// ---------------- SPMM1 + ReLU: H1[r] = relu(sum_e w * H0[col]) --------------
// block per row, 128 threads, float4 per thread (512 cols)
__global__ __launch_bounds__(128)
void spmm1_kernel() {
    int r = blockIdx.x;
    int t = threadIdx.x;
    const float4* H0 = (const float4*)g_H0;
    float4 acc = make_float4(0.f, 0.f, 0.f, 0.f);
    int beg = g_rowptr[r], end = g_rowptr[r + 1];
    int e = beg;
    for (; e + 1 < end; e += 2) {
        int c0 = g_cols[e], c1 = g_cols[e + 1];
        float w0 = g_w[e], w1 = g_w[e + 1];
        float4 v0 = H0[(size_t)c0 * 128 + t];
        float4 v1 = H0[(size_t)c1 * 128 + t];
        acc.x += w0 * v0.x + w1 * v1.x;
        acc.y += w0 * v0.y + w1 * v1.y;
        acc.z += w0 * v0.z + w1 * v1.z;
        acc.w += w0 * v0.w + w1 * v1.w;
    }
    if (e < end) {
        int c0 = g_cols[e];
        float w0 = g_w[e];
        float4 v0 = H0[(size_t)c0 * 128 + t];
        acc.x += w0 * v0.x; acc.y += w0 * v0.y;
        acc.z += w0 * v0.z; acc.w += w0 * v0.w;
    }
    acc.x = fmaxf(acc.x, 0.f); acc.y = fmaxf(acc.y, 0.f);
    acc.z = fmaxf(acc.z, 0.f); acc.w = fmaxf(acc.w, 0.f);
    ((float4*)g_H1)[(size_t)r * 128 + t] = acc;
}

// ---------------- GEMM2: H2[row][0:10]=H1a@W2_1+b, [10:20]=H1b@W2_2+b --------
__global__ __launch_bounds__(256)
void gemm2_kernel(const float* __restrict__ Wa, const float* __restrict__ ba,
                  const float* __restrict__ Wb, const float* __restrict__ bb) {
    __shared__ float Ws[2 * NH * NC];  // 5120 floats = 20KB
    for (int i = threadIdx.x; i < NH * NC; i += 256) {
        Ws[i]            = Wa[i];
        Ws[NH * NC + i]  = Wb[i];
    }
    __syncthreads();

    int i = blockIdx.x * blockDim.x + threadIdx.x;
    if (i >= NN * 2 * NC) return;
    int row = i / (2 * NC);
    int c   = i - row * (2 * NC);
    int net = c / NC;
    int cc  = c - net * NC;

    const float* W = Ws + net * NH * NC;
    const float4* h = (const float4*)(g_H1 + (size_t)row * HID2 + net * NH);
    float acc = net ? bb[cc] : ba[cc];
#pragma unroll 4
    for (int k4 = 0; k4 < NH / 4; k4++) {
        float4 v = h[k4];
        int kb = k4 * 4;
        acc += v.x * W[(kb + 0) * NC + cc];
        acc += v.y * W[(kb + 1) * NC + cc];
        acc += v.z * W[(kb + 2) * NC + cc];
        acc += v.w * W[(kb + 3) * NC + cc];
    }
    g_H2[i] = acc;
}

// ---------------- SPMM2 -> output: warp per row, 20 active lanes -------------
__global__ __launch_bounds__(256)
void spmm2_kernel(float* __restrict__ out) {
    int gid  = blockIdx.x * blockDim.x + threadIdx.x;
    int warp = gid >> 5;
    int lane = threadIdx.x & 31;
    if (warp >= NN) return;
    int beg = g_rowptr[warp], end = g_rowptr[warp + 1];
    float acc = 0.f;
    for (int e = beg; e < end; e++) {
        int c = g_cols[e];
        float w = g_w[e];
        if (lane < 2 * NC) acc += w * g_H2[(size_t)c * 2 * NC + lane];
    }
    if (lane < NC)
        out[(size_t)warp * NC + lane] = acc;                    // x1
    else if (lane < 2 * NC)
        out[(size_t)NN * NC + (size_t)warp * NC + (lane - NC)] = acc;  // x2
}

// ---------------- launch -----------------------------------------------------
extern "C" void kernel_launch(void* const* d_in, const int* in_sizes, int n_in,
                              void* d_out, int out_size) {
    const float* x    = (const float*)d_in[0];
    const void*  ei   = d_in[1];
    const float* ew   = (const float*)d_in[2];
    const float* W1a  = (const float*)d_in[3];
    const float* b1a  = (const float*)d_in[4];
    const float* W2a  = (const float*)d_in[5];
    const float* b2a  = (const float*)d_in[6];
    const float* W1b  = (const float*)d_in[7];
    const float* b1b  = (const float*)d_in[8];
    const float* W2b  = (const float*)d_in[9];
    const float* b2b  = (const float*)d_in[10];
    float* out = (float*)d_out;

    // dtype detect + CSR build (graph-capturable, kernels only)
    zero_kernel<<<(NN + 255) / 256, 256>>>();
    detect_kernel<<<(NE + 255) / 256, 256>>>((const long long*)ei);
    count_kernel<<<(NE + 255) / 256, 256>>>(ei);
    scan_kernel<<<1, 1024>>>();
    scatter_kernel<<<(NE + 255) / 256, 256>>>(ei, ew);

    // layer 1 linear (both nets fused along N)
    dim3 g1(HID2 / 128, (NN + 127) / 128);
    gemm1_kernel<<<g1, 256>>>(x, W1a, b1a, W1b, b1b);

    // propagate + relu
    spmm1_kernel<<<NN, 128>>>();

    // layer 2 linear
    gemm2_kernel<<<(NN * 2 * NC + 255) / 256, 256>>>(W2a, b2a, W2b, b2b);

    // propagate -> outputs
    spmm2_kernel<<<(NN * 32 + 255) / 256, 256>>>(out);
}

// round 6
// speedup vs baseline: 1.4088x; 1.4088x over previous
#include <cuda_runtime.h>
#include <cuda_bf16.h>
#include <cstdint>

#define NN 50000
#define NE 800000
#define NF 500
#define NH 256
#define NC 10
#define HID2 512   // both networks' hidden concatenated
#define KPAD 512   // padded K for tensor-core GEMM

// ---------------- scratch (device globals; no runtime allocation) -----------
__device__ __align__(256) float g_H0[NN * HID2];   // x@W1 + b1 (both nets)
__device__ __align__(256) float g_H1[NN * HID2];   // relu(spmm(H0))
__device__ __align__(256) float g_H2[NN * 2 * NC]; // H1@W2 + b2 (both nets)
__device__ __align__(256) __nv_bfloat16 g_A0[NN * KPAD];   // hi(x), K-padded
__device__ __align__(256) __nv_bfloat16 g_A1[NN * KPAD];   // lo(x)
__device__ __align__(256) __nv_bfloat16 g_B0[HID2 * KPAD]; // hi(W^T) [n][k]
__device__ __align__(256) __nv_bfloat16 g_B1[HID2 * KPAD]; // lo(W^T)
__device__ __align__(256) float g_bias[HID2];
__device__ int   g_rowptr[NN + 1];
__device__ int   g_cnt[NN];
__device__ int   g_fill[NN];
__device__ int   g_btot[256];
__device__ int   g_cols[NE];
__device__ float g_w[NE];
__device__ int   g_is64;

// ================= helpers ===================================================
__device__ __forceinline__ uint32_t smem_u32(const void* p) {
    uint32_t a;
    asm("{ .reg .u64 t; cvta.to.shared.u64 t, %1; cvt.u32.u64 %0, t; }"
        : "=r"(a) : "l"(p));
    return a;
}
#define SMEM_SWIZZLE_128B(off) ((off) ^ (((off) >> 3) & 0x70))

__device__ __forceinline__ void ldsm_x4(uint32_t* d, uint32_t addr) {
    asm volatile("ldmatrix.sync.aligned.m8n8.x4.shared.b16 {%0,%1,%2,%3}, [%4];"
                 : "=r"(d[0]), "=r"(d[1]), "=r"(d[2]), "=r"(d[3]) : "r"(addr));
}
__device__ __forceinline__ void mma16816(float* c, const uint32_t* a,
                                         uint32_t b0, uint32_t b1) {
    asm volatile("mma.sync.aligned.m16n8k16.row.col.f32.bf16.bf16.f32 "
                 "{%0,%1,%2,%3}, {%4,%5,%6,%7}, {%8,%9}, {%0,%1,%2,%3};"
                 : "+f"(c[0]), "+f"(c[1]), "+f"(c[2]), "+f"(c[3])
                 : "r"(a[0]), "r"(a[1]), "r"(a[2]), "r"(a[3]), "r"(b0), "r"(b1));
}

// ---------------- dtype detect + CSR build ----------------------------------
__global__ void zero_kernel() {
    int i = blockIdx.x * blockDim.x + threadIdx.x;
    if (i < NN) { g_cnt[i] = 0; g_fill[i] = 0; }
    if (i == 0) g_is64 = 1;
}

__global__ void detect_kernel(const long long* __restrict__ ei) {
    int e = blockIdx.x * blockDim.x + threadIdx.x;
    if (e < NE) {
        long long v = ei[e];
        if (v < 0 || v >= NN) atomicAnd(&g_is64, 0);
    }
}

__device__ __forceinline__ int edge_row(const void* ei, int e) {
    return g_is64 ? (int)((const long long*)ei)[e] : ((const int*)ei)[e];
}
__device__ __forceinline__ int edge_col(const void* ei, int e) {
    return g_is64 ? (int)((const long long*)ei)[NE + e] : ((const int*)ei)[NE + e];
}

__global__ void count_kernel(const void* __restrict__ ei) {
    int e = blockIdx.x * blockDim.x + threadIdx.x;
    if (e < NE) atomicAdd(&g_cnt[edge_row(ei, e)], 1);
}

// 3-phase parallel scan
#define SCAN_NB ((NN + 255) / 256)   // 196
__global__ void scan1_kernel() {
    __shared__ int sh[256];
    int t = threadIdx.x, b = blockIdx.x;
    int i = b * 256 + t;
    int v = (i < NN) ? g_cnt[i] : 0;
    sh[t] = v; __syncthreads();
    for (int off = 1; off < 256; off <<= 1) {
        int u = (t >= off) ? sh[t - off] : 0;
        __syncthreads(); sh[t] += u; __syncthreads();
    }
    if (i < NN) g_rowptr[i] = sh[t] - v;
    if (t == 255) g_btot[b] = sh[255];
}
__global__ void scan2_kernel() {
    __shared__ int sh[256];
    int t = threadIdx.x;
    int v = (t < SCAN_NB) ? g_btot[t] : 0;
    sh[t] = v; __syncthreads();
    for (int off = 1; off < 256; off <<= 1) {
        int u = (t >= off) ? sh[t - off] : 0;
        __syncthreads(); sh[t] += u; __syncthreads();
    }
    if (t < SCAN_NB) g_btot[t] = sh[t] - v;
    if (t == SCAN_NB - 1) g_rowptr[NN] = sh[t];
}
__global__ void scan3_kernel() {
    int i = blockIdx.x * blockDim.x + threadIdx.x;
    if (i < NN) g_rowptr[i] += g_btot[i >> 8];
}

__global__ void scatter_kernel(const void* __restrict__ ei,
                               const float* __restrict__ ew) {
    int e = blockIdx.x * blockDim.x + threadIdx.x;
    if (e < NE) {
        int r = edge_row(ei, e);
        int c = edge_col(ei, e);
        int pos = g_rowptr[r] + atomicAdd(&g_fill[r], 1);
        g_cols[pos] = c;
        g_w[pos]    = ew[e];
    }
}

// ---------------- bf16x2 split conversions -----------------------------------
__device__ __forceinline__ uint32_t split_pack_hi(float a, float b,
                                                  float& ra, float& rb) {
    __nv_bfloat16 ha = __float2bfloat16_rn(a);
    __nv_bfloat16 hb = __float2bfloat16_rn(b);
    ra = a - __bfloat162float(ha);
    rb = b - __bfloat162float(hb);
    return (uint32_t)__bfloat16_as_ushort(ha) |
           ((uint32_t)__bfloat16_as_ushort(hb) << 16);
}
__device__ __forceinline__ uint32_t pack_bf16(float a, float b) {
    return (uint32_t)__bfloat16_as_ushort(__float2bfloat16_rn(a)) |
           ((uint32_t)__bfloat16_as_ushort(__float2bfloat16_rn(b)) << 16);
}

__global__ void convertA_kernel(const float* __restrict__ x) {
    int idx = blockIdx.x * blockDim.x + threadIdx.x;   // row*256 + k2
    if (idx >= NN * (KPAD / 2)) return;
    int row = idx >> 8;
    int k2  = idx & 255;
    float2 v = make_float2(0.f, 0.f);
    if (k2 < NF / 2)
        v = *(const float2*)(x + (size_t)row * NF + 2 * k2);
    float ra, rb;
    uint32_t hi = split_pack_hi(v.x, v.y, ra, rb);
    ((uint32_t*)g_A0)[idx] = hi;
    ((uint32_t*)g_A1)[idx] = pack_bf16(ra, rb);
}

__global__ void convertB_kernel(const float* __restrict__ Wa, const float* __restrict__ ba,
                                const float* __restrict__ Wb, const float* __restrict__ bb) {
    int idx = blockIdx.x * blockDim.x + threadIdx.x;   // n*256 + k2
    if (idx >= HID2 * (KPAD / 2)) return;
    int n  = idx >> 8;
    int k2 = idx & 255;
    int net = n >> 8;
    int col = n & (NH - 1);
    const float* W = net ? Wb : Wa;
    int k = 2 * k2;
    float a = (k     < NF) ? W[(size_t)k       * NH + col] : 0.f;
    float b = (k + 1 < NF) ? W[(size_t)(k + 1) * NH + col] : 0.f;
    float ra, rb;
    uint32_t hi = split_pack_hi(a, b, ra, rb);
    ((uint32_t*)g_B0)[idx] = hi;
    ((uint32_t*)g_B1)[idx] = pack_bf16(ra, rb);
    if (k2 == 0) g_bias[n] = net ? bb[col] : ba[col];
}

// ---------------- GEMM1 (mma.sync bf16x2 split): H0 = A@B^T + bias -----------
// CTA 128x128, BK=64. 8 warps (2m x 4n), warp tile 64x32 of m16n8k16 frags.
#define SM_BIAS  0
#define SM_A0    1024
#define SM_A1    (SM_A0 + 16384)
#define SM_B0    (SM_A1 + 16384)
#define SM_B1    (SM_B0 + 16384)
#define GEMM1_SMEM (SM_B1 + 16384)   // 66560 bytes

__device__ __forceinline__ void load_tile64(const __nv_bfloat16* __restrict__ src,
                                            int row0, int row_limit, int k0,
                                            char* tile, int tid) {
    int row  = tid >> 1;      // 0..127
    int half = tid & 1;       // which 64B half of the 128B row
    int grow = row0 + row;
    const __nv_bfloat16* p = src + (size_t)grow * KPAD + k0 + half * 32;
#pragma unroll
    for (int j = 0; j < 4; j++) {
        uint32_t byte_off = (uint32_t)(row * 128 + half * 64 + j * 16);
        uint32_t sw = SMEM_SWIZZLE_128B(byte_off);
        uint4 v = make_uint4(0u, 0u, 0u, 0u);
        if (grow < row_limit) v = *(const uint4*)(p + j * 8);
        *(uint4*)(tile + sw) = v;
    }
}

// ldmatrix address for A frag (m16k16) at (m_local, k0) in a 128-row SW128 tile
__device__ __forceinline__ uint32_t addrA(uint32_t base, int m_local, int k0, int lane) {
    int mat = lane >> 3, r = lane & 7;
    int m = m_local + r + (mat & 1) * 8;
    int k = k0 + (mat >> 1) * 8;
    return base + (uint32_t)(m * 128 + (((k >> 3) ^ (m & 7)) << 4));
}
// ldmatrix address for B double-frag (n16k16) at (n_local, k0)
__device__ __forceinline__ uint32_t addrB(uint32_t base, int n_local, int k0, int lane) {
    int mat = lane >> 3, r = lane & 7;
    int n = n_local + r + ((mat >> 1) & 1) * 8;
    int k = k0 + (mat & 1) * 8;
    return base + (uint32_t)(n * 128 + (((k >> 3) ^ (n & 7)) << 4));
}

__global__ __launch_bounds__(256, 2)
void gemm1_mma_kernel() {
    extern __shared__ char smem[];
    uint32_t sb = smem_u32(smem);
    int tid  = threadIdx.x;
    int lane = tid & 31, wid = tid >> 5;
    int warp_m = wid & 1;        // 0..1 -> 64-row slab
    int warp_n = wid >> 1;       // 0..3 -> 32-col slab
    int nbase = blockIdx.x * 128;
    int mbase = blockIdx.y * 128;

    if (tid < 32)
        ((float4*)(smem + SM_BIAS))[tid] = ((const float4*)(g_bias + nbase))[tid];

    float acc[4][4][4];
#pragma unroll
    for (int i = 0; i < 4; i++)
#pragma unroll
        for (int j = 0; j < 4; j++)
#pragma unroll
            for (int q = 0; q < 4; q++) acc[i][j][q] = 0.f;

    uint32_t sa0 = sb + SM_A0, sa1 = sb + SM_A1;
    uint32_t sb0 = sb + SM_B0, sb1 = sb + SM_B1;

    for (int kt = 0; kt < 8; kt++) {
        __syncthreads();
        int k0c = kt * 64;
        load_tile64(g_A0, mbase, NN,   k0c, smem + SM_A0, tid);
        load_tile64(g_A1, mbase, NN,   k0c, smem + SM_A1, tid);
        load_tile64(g_B0, nbase, HID2, k0c, smem + SM_B0, tid);
        load_tile64(g_B1, nbase, HID2, k0c, smem + SM_B1, tid);
        __syncthreads();

#pragma unroll
        for (int ks = 0; ks < 4; ks++) {
            int k0 = ks * 16;
            uint32_t a[4][4], b[2][4];
            // pass 1: A0 * B0
#pragma unroll
            for (int mf = 0; mf < 4; mf++)
                ldsm_x4(a[mf], addrA(sa0, warp_m * 64 + mf * 16, k0, lane));
#pragma unroll
            for (int g = 0; g < 2; g++)
                ldsm_x4(b[g], addrB(sb0, warp_n * 32 + g * 16, k0, lane));
#pragma unroll
            for (int mf = 0; mf < 4; mf++)
#pragma unroll
                for (int nf = 0; nf < 4; nf++)
                    mma16816(acc[mf][nf], a[mf],
                             b[nf >> 1][(nf & 1) * 2], b[nf >> 1][(nf & 1) * 2 + 1]);
            // pass 2: A1 * B0
#pragma unroll
            for (int mf = 0; mf < 4; mf++)
                ldsm_x4(a[mf], addrA(sa1, warp_m * 64 + mf * 16, k0, lane));
#pragma unroll
            for (int mf = 0; mf < 4; mf++)
#pragma unroll
                for (int nf = 0; nf < 4; nf++)
                    mma16816(acc[mf][nf], a[mf],
                             b[nf >> 1][(nf & 1) * 2], b[nf >> 1][(nf & 1) * 2 + 1]);
            // pass 3: A0 * B1
#pragma unroll
            for (int mf = 0; mf < 4; mf++)
                ldsm_x4(a[mf], addrA(sa0, warp_m * 64 + mf * 16, k0, lane));
#pragma unroll
            for (int g = 0; g < 2; g++)
                ldsm_x4(b[g], addrB(sb1, warp_n * 32 + g * 16, k0, lane));
#pragma unroll
            for (int mf = 0; mf < 4; mf++)
#pragma unroll
                for (int nf = 0; nf < 4; nf++)
                    mma16816(acc[mf][nf], a[mf],
                             b[nf >> 1][(nf & 1) * 2], b[nf >> 1][(nf & 1) * 2 + 1]);
        }
    }

    // epilogue: C[m0 + lane/4][n0 + 2*(lane%4)] pairs, second pair at m+8
    const float* bs = (const float*)(smem + SM_BIAS);
#pragma unroll
    for (int mf = 0; mf < 4; mf++) {
#pragma unroll
        for (int nf = 0; nf < 4; nf++) {
            int ncol = warp_n * 32 + nf * 8 + (lane & 3) * 2;
            float bx = bs[ncol], by = bs[ncol + 1];
            int r0 = mbase + warp_m * 64 + mf * 16 + (lane >> 2);
            if (r0 < NN) {
                float2 v = make_float2(acc[mf][nf][0] + bx, acc[mf][nf][1] + by);
                *(float2*)(g_H0 + (size_t)r0 * HID2 + nbase + ncol) = v;
            }
            int r1 = r0 + 8;
            if (r1 < NN) {
                float2 v = make_float2(acc[mf][nf][2] + bx, acc[mf][nf][3] + by);
                *(float2*)(g_H0 + (size_t)r1 * HID2 + nbase + ncol) = v;
            }
        }
    }
}

// ---------------- SPMM1 + ReLU: H1[r] = relu(sum_e w * H0[col]) --------------
__global__ __launch_bounds__(128)
void spmm1_kernel() {
    int r = blockIdx.x;
    int t = threadIdx.x;
    const float4* H0 = (const float4*)g_H0;
    float4 acc = make_float4(0.f, 0.f, 0.f, 0.f);
    int beg = g_rowptr[r], end = g_rowptr[r + 1];
    int e = beg;
    for (; e + 3 < end; e += 4) {
        int c0 = __ldg(&g_cols[e]),     c1 = __ldg(&g_cols[e + 1]);
        int c2 = __ldg(&g_cols[e + 2]), c3 = __ldg(&g_cols[e + 3]);
        float w0 = __ldg(&g_w[e]),     w1 = __ldg(&g_w[e + 1]);
        float w2 = __ldg(&g_w[e + 2]), w3 = __ldg(&g_w[e + 3]);
        float4 v0 = H0[(size_t)c0 * 128 + t];
        float4 v1 = H0[(size_t)c1 * 128 + t];
        float4 v2 = H0[(size_t)c2 * 128 + t];
        float4 v3 = H0[(size_t)c3 * 128 + t];
        acc.x += w0 * v0.x + w1 * v1.x + w2 * v2.x + w3 * v3.x;
        acc.y += w0 * v0.y + w1 * v1.y + w2 * v2.y + w3 * v3.y;
        acc.z += w0 * v0.z + w1 * v1.z + w2 * v2.z + w3 * v3.z;
        acc.w += w0 * v0.w + w1 * v1.w + w2 * v2.w + w3 * v3.w;
    }
    for (; e < end; e++) {
        int c0 = __ldg(&g_cols[e]);
        float w0 = __ldg(&g_w[e]);
        float4 v0 = H0[(size_t)c0 * 128 + t];
        acc.x += w0 * v0.x; acc.y += w0 * v0.y;
        acc.z += w0 * v0.z; acc.w += w0 * v0.w;
    }
    acc.x = fmaxf(acc.x, 0.f); acc.y = fmaxf(acc.y, 0.f);
    acc.z = fmaxf(acc.z, 0.f); acc.w = fmaxf(acc.w, 0.f);
    ((float4*)g_H1)[(size_t)r * 128 + t] = acc;
}

// ---------------- GEMM2: H2[row][0:10]=H1a@W2_1+b, [10:20]=H1b@W2_2+b --------
__global__ __launch_bounds__(256)
void gemm2_kernel(const float* __restrict__ Wa, const float* __restrict__ ba,
                  const float* __restrict__ Wb, const float* __restrict__ bb) {
    __shared__ float Ws[2 * NH * NC];
    for (int i = threadIdx.x; i < NH * NC; i += 256) {
        Ws[i]           = Wa[i];
        Ws[NH * NC + i] = Wb[i];
    }
    __syncthreads();

    int i = blockIdx.x * blockDim.x + threadIdx.x;
    if (i >= NN * 2 * NC) return;
    int row = i / (2 * NC);
    int c   = i - row * (2 * NC);
    int net = c / NC;
    int cc  = c - net * NC;

    const float* W = Ws + net * NH * NC;
    const float4* h = (const float4*)(g_H1 + (size_t)row * HID2 + net * NH);
    float acc = net ? bb[cc] : ba[cc];
#pragma unroll 4
    for (int k4 = 0; k4 < NH / 4; k4++) {
        float4 v = h[k4];
        int kb = k4 * 4;
        acc += v.x * W[(kb + 0) * NC + cc];
        acc += v.y * W[(kb + 1) * NC + cc];
        acc += v.z * W[(kb + 2) * NC + cc];
        acc += v.w * W[(kb + 3) * NC + cc];
    }
    g_H2[i] = acc;
}

// ---------------- SPMM2 -> output: warp per row, 20 active lanes -------------
__global__ __launch_bounds__(256)
void spmm2_kernel(float* __restrict__ out) {
    int gid  = blockIdx.x * blockDim.x + threadIdx.x;
    int warp = gid >> 5;
    int lane = threadIdx.x & 31;
    if (warp >= NN) return;
    int beg = g_rowptr[warp], end = g_rowptr[warp + 1];
    float acc = 0.f;
    for (int e = beg; e < end; e++) {
        int c = __ldg(&g_cols[e]);
        float w = __ldg(&g_w[e]);
        if (lane < 2 * NC) acc += w * g_H2[(size_t)c * 2 * NC + lane];
    }
    if (lane < NC)
        out[(size_t)warp * NC + lane] = acc;
    else if (lane < 2 * NC)
        out[(size_t)NN * NC + (size_t)warp * NC + (lane - NC)] = acc;
}

// ---------------- launch -----------------------------------------------------
extern "C" void kernel_launch(void* const* d_in, const int* in_sizes, int n_in,
                              void* d_out, int out_size) {
    const float* x    = (const float*)d_in[0];
    const void*  ei   = d_in[1];
    const float* ew   = (const float*)d_in[2];
    const float* W1a  = (const float*)d_in[3];
    const float* b1a  = (const float*)d_in[4];
    const float* W2a  = (const float*)d_in[5];
    const float* b2a  = (const float*)d_in[6];
    const float* W1b  = (const float*)d_in[7];
    const float* b1b  = (const float*)d_in[8];
    const float* W2b  = (const float*)d_in[9];
    const float* b2b  = (const float*)d_in[10];
    float* out = (float*)d_out;

    cudaFuncSetAttribute(gemm1_mma_kernel,
                         cudaFuncAttributeMaxDynamicSharedMemorySize, GEMM1_SMEM);

    // CSR build (dtype-safe, graph-capturable)
    zero_kernel<<<(NN + 255) / 256, 256>>>();
    detect_kernel<<<(NE + 255) / 256, 256>>>((const long long*)ei);
    count_kernel<<<(NE + 255) / 256, 256>>>(ei);
    scan1_kernel<<<SCAN_NB, 256>>>();
    scan2_kernel<<<1, 256>>>();
    scan3_kernel<<<(NN + 255) / 256, 256>>>();
    scatter_kernel<<<(NE + 255) / 256, 256>>>(ei, ew);

    // bf16x2 split conversions
    convertA_kernel<<<(NN * (KPAD / 2) + 255) / 256, 256>>>(x);
    convertB_kernel<<<(HID2 * (KPAD / 2) + 255) / 256, 256>>>(W1a, b1a, W1b, b1b);

    // layer 1 linear on tensor cores (mma.sync bf16 split)
    dim3 g1(HID2 / 128, (NN + 127) / 128);
    gemm1_mma_kernel<<<g1, 256, GEMM1_SMEM>>>();

    // propagate + relu
    spmm1_kernel<<<NN, 128>>>();

    // layer 2 linear
    gemm2_kernel<<<(NN * 2 * NC + 255) / 256, 256>>>(W2a, b2a, W2b, b2b);

    // propagate -> outputs
    spmm2_kernel<<<(NN * 32 + 255) / 256, 256>>>(out);
}

// round 7
// speedup vs baseline: 1.4677x; 1.0418x over previous
#include <cuda_runtime.h>
#include <cuda_bf16.h>
#include <cstdint>

#define NN 50000
#define NE 800000
#define NF 500
#define NH 256
#define NC 10
#define HID2 512   // both networks' hidden concatenated
#define KPAD 512   // padded K for tensor-core GEMM

// ---------------- scratch (device globals; no runtime allocation) -----------
__device__ __align__(256) float g_H0[NN * HID2];   // x@W1 + b1 (both nets)
__device__ __align__(256) float g_H1[NN * HID2];   // relu(spmm(H0))
__device__ __align__(256) float g_H2[NN * 2 * NC]; // H1@W2 + b2 (both nets)
__device__ __align__(256) __nv_bfloat16 g_A0[NN * KPAD];   // hi(x), K-padded
__device__ __align__(256) __nv_bfloat16 g_A1[NN * KPAD];   // lo(x)
__device__ __align__(256) __nv_bfloat16 g_B0[HID2 * KPAD]; // hi(W^T) [n][k]
__device__ __align__(256) __nv_bfloat16 g_B1[HID2 * KPAD]; // lo(W^T)
__device__ __align__(256) float g_bias[HID2];
__device__ int   g_rowptr[NN + 1];
__device__ int   g_cnt[NN];
__device__ int   g_fill[NN];
__device__ int   g_btot[256];
__device__ int   g_cols[NE];
__device__ float g_w[NE];
__device__ int   g_is64;

// ================= helpers ===================================================
__device__ __forceinline__ uint32_t smem_u32(const void* p) {
    uint32_t a;
    asm("{ .reg .u64 t; cvta.to.shared.u64 t, %1; cvt.u32.u64 %0, t; }"
        : "=r"(a) : "l"(p));
    return a;
}
#define SMEM_SWIZZLE_128B(off) ((off) ^ (((off) >> 3) & 0x70))

__device__ __forceinline__ void ldsm_x4(uint32_t* d, uint32_t addr) {
    asm volatile("ldmatrix.sync.aligned.m8n8.x4.shared.b16 {%0,%1,%2,%3}, [%4];"
                 : "=r"(d[0]), "=r"(d[1]), "=r"(d[2]), "=r"(d[3]) : "r"(addr));
}
__device__ __forceinline__ void mma16816(float* c, const uint32_t* a,
                                         uint32_t b0, uint32_t b1) {
    asm volatile("mma.sync.aligned.m16n8k16.row.col.f32.bf16.bf16.f32 "
                 "{%0,%1,%2,%3}, {%4,%5,%6,%7}, {%8,%9}, {%0,%1,%2,%3};"
                 : "+f"(c[0]), "+f"(c[1]), "+f"(c[2]), "+f"(c[3])
                 : "r"(a[0]), "r"(a[1]), "r"(a[2]), "r"(a[3]), "r"(b0), "r"(b1));
}
__device__ __forceinline__ void cp_async16(uint32_t dst, const void* src, int src_sz) {
    asm volatile("cp.async.cg.shared.global [%0], [%1], 16, %2;"
                 :: "r"(dst), "l"(src), "r"(src_sz) : "memory");
}
#define CP_COMMIT() asm volatile("cp.async.commit_group;" ::: "memory")
#define CP_WAIT1()  asm volatile("cp.async.wait_group 1;" ::: "memory")
#define CP_WAIT0()  asm volatile("cp.async.wait_group 0;" ::: "memory")

// ---------------- dtype detect + CSR build ----------------------------------
__global__ void zero_kernel() {
    int i = blockIdx.x * blockDim.x + threadIdx.x;
    if (i < NN) { g_cnt[i] = 0; g_fill[i] = 0; }
    if (i == 0) g_is64 = 1;
}

__global__ void detect_kernel(const long long* __restrict__ ei) {
    int e = blockIdx.x * blockDim.x + threadIdx.x;
    if (e < NE) {
        long long v = ei[e];
        if (v < 0 || v >= NN) atomicAnd(&g_is64, 0);
    }
}

__device__ __forceinline__ int edge_row(const void* ei, int e) {
    return g_is64 ? (int)((const long long*)ei)[e] : ((const int*)ei)[e];
}
__device__ __forceinline__ int edge_col(const void* ei, int e) {
    return g_is64 ? (int)((const long long*)ei)[NE + e] : ((const int*)ei)[NE + e];
}

__global__ void count_kernel(const void* __restrict__ ei) {
    int e = blockIdx.x * blockDim.x + threadIdx.x;
    if (e < NE) atomicAdd(&g_cnt[edge_row(ei, e)], 1);
}

// 3-phase parallel scan
#define SCAN_NB ((NN + 255) / 256)   // 196
__global__ void scan1_kernel() {
    __shared__ int sh[256];
    int t = threadIdx.x, b = blockIdx.x;
    int i = b * 256 + t;
    int v = (i < NN) ? g_cnt[i] : 0;
    sh[t] = v; __syncthreads();
    for (int off = 1; off < 256; off <<= 1) {
        int u = (t >= off) ? sh[t - off] : 0;
        __syncthreads(); sh[t] += u; __syncthreads();
    }
    if (i < NN) g_rowptr[i] = sh[t] - v;
    if (t == 255) g_btot[b] = sh[255];
}
__global__ void scan2_kernel() {
    __shared__ int sh[256];
    int t = threadIdx.x;
    int v = (t < SCAN_NB) ? g_btot[t] : 0;
    sh[t] = v; __syncthreads();
    for (int off = 1; off < 256; off <<= 1) {
        int u = (t >= off) ? sh[t - off] : 0;
        __syncthreads(); sh[t] += u; __syncthreads();
    }
    if (t < SCAN_NB) g_btot[t] = sh[t] - v;
    if (t == SCAN_NB - 1) g_rowptr[NN] = sh[t];
}
__global__ void scan3_kernel() {
    int i = blockIdx.x * blockDim.x + threadIdx.x;
    if (i < NN) g_rowptr[i] += g_btot[i >> 8];
}

__global__ void scatter_kernel(const void* __restrict__ ei,
                               const float* __restrict__ ew) {
    int e = blockIdx.x * blockDim.x + threadIdx.x;
    if (e < NE) {
        int r = edge_row(ei, e);
        int c = edge_col(ei, e);
        int pos = g_rowptr[r] + atomicAdd(&g_fill[r], 1);
        g_cols[pos] = c;
        g_w[pos]    = ew[e];
    }
}

// ---------------- bf16x2 split conversions -----------------------------------
__device__ __forceinline__ uint32_t split_pack_hi(float a, float b,
                                                  float& ra, float& rb) {
    __nv_bfloat16 ha = __float2bfloat16_rn(a);
    __nv_bfloat16 hb = __float2bfloat16_rn(b);
    ra = a - __bfloat162float(ha);
    rb = b - __bfloat162float(hb);
    return (uint32_t)__bfloat16_as_ushort(ha) |
           ((uint32_t)__bfloat16_as_ushort(hb) << 16);
}
__device__ __forceinline__ uint32_t pack_bf16(float a, float b) {
    return (uint32_t)__bfloat16_as_ushort(__float2bfloat16_rn(a)) |
           ((uint32_t)__bfloat16_as_ushort(__float2bfloat16_rn(b)) << 16);
}

__global__ void convertA_kernel(const float* __restrict__ x) {
    int idx = blockIdx.x * blockDim.x + threadIdx.x;   // row*256 + k2
    if (idx >= NN * (KPAD / 2)) return;
    int row = idx >> 8;
    int k2  = idx & 255;
    float2 v = make_float2(0.f, 0.f);
    if (k2 < NF / 2)
        v = *(const float2*)(x + (size_t)row * NF + 2 * k2);
    float ra, rb;
    uint32_t hi = split_pack_hi(v.x, v.y, ra, rb);
    ((uint32_t*)g_A0)[idx] = hi;
    ((uint32_t*)g_A1)[idx] = pack_bf16(ra, rb);
}

__global__ void convertB_kernel(const float* __restrict__ Wa, const float* __restrict__ ba,
                                const float* __restrict__ Wb, const float* __restrict__ bb) {
    int idx = blockIdx.x * blockDim.x + threadIdx.x;   // n*256 + k2
    if (idx >= HID2 * (KPAD / 2)) return;
    int n  = idx >> 8;
    int k2 = idx & 255;
    int net = n >> 8;
    int col = n & (NH - 1);
    const float* W = net ? Wb : Wa;
    int k = 2 * k2;
    float a = (k     < NF) ? W[(size_t)k       * NH + col] : 0.f;
    float b = (k + 1 < NF) ? W[(size_t)(k + 1) * NH + col] : 0.f;
    float ra, rb;
    uint32_t hi = split_pack_hi(a, b, ra, rb);
    ((uint32_t*)g_B0)[idx] = hi;
    ((uint32_t*)g_B1)[idx] = pack_bf16(ra, rb);
    if (k2 == 0) g_bias[n] = net ? bb[col] : ba[col];
}

// ---------------- GEMM1 (mma.sync, cp.async 2-stage): H0 = A@B^T + bias ------
// CTA tile M=64, N=128, BK=64. 8 warps (2m x 4n), warp tile 32x32.
#define SM_BIAS   0
#define SM_STAGE0 1024
#define STG_A0    0
#define STG_A1    8192
#define STG_B0    16384
#define STG_B1    32768
#define STAGE_BYTES 49152
#define GEMM1_SMEM (SM_STAGE0 + 2 * STAGE_BYTES)   // 99328 bytes

// load one 2-stage buffer: A tiles 64x128B (2 chunks/thread), B tiles 128x128B (4)
__device__ __forceinline__ void load_stage(uint32_t stage_base, int mbase, int nbase,
                                           int k0, int tid) {
    // A0 / A1 : 64 rows x 128 bytes
#pragma unroll
    for (int p = 0; p < 2; p++) {
        uint32_t off = (uint32_t)(tid + p * 256) * 16;   // 0..8176
        int row = off >> 7, inner = off & 127;
        int grow = mbase + row;
        int ok = (grow < NN) ? 16 : 0;
        int gr = (grow < NN) ? grow : (NN - 1);
        uint32_t sw = SMEM_SWIZZLE_128B(off);
        cp_async16(stage_base + STG_A0 + sw,
                   (const char*)g_A0 + ((size_t)gr * KPAD + k0) * 2 + inner, ok);
        cp_async16(stage_base + STG_A1 + sw,
                   (const char*)g_A1 + ((size_t)gr * KPAD + k0) * 2 + inner, ok);
    }
    // B0 / B1 : 128 rows x 128 bytes (always in-bounds)
#pragma unroll
    for (int p = 0; p < 4; p++) {
        uint32_t off = (uint32_t)(tid + p * 256) * 16;   // 0..16368
        int row = off >> 7, inner = off & 127;
        int nrow = nbase + row;
        uint32_t sw = SMEM_SWIZZLE_128B(off);
        cp_async16(stage_base + STG_B0 + sw,
                   (const char*)g_B0 + ((size_t)nrow * KPAD + k0) * 2 + inner, 16);
        cp_async16(stage_base + STG_B1 + sw,
                   (const char*)g_B1 + ((size_t)nrow * KPAD + k0) * 2 + inner, 16);
    }
}

// ldmatrix address for A frag (m16k16) at (m_local, k0) in a 128B-row tile
__device__ __forceinline__ uint32_t addrA(uint32_t base, int m_local, int k0, int lane) {
    int mat = lane >> 3, r = lane & 7;
    int m = m_local + r + (mat & 1) * 8;
    int k = k0 + (mat >> 1) * 8;
    return base + (uint32_t)(m * 128 + (((k >> 3) ^ (m & 7)) << 4));
}
// ldmatrix address for B double-frag (n16k16) at (n_local, k0)
__device__ __forceinline__ uint32_t addrB(uint32_t base, int n_local, int k0, int lane) {
    int mat = lane >> 3, r = lane & 7;
    int n = n_local + r + ((mat >> 1) & 1) * 8;
    int k = k0 + (mat & 1) * 8;
    return base + (uint32_t)(n * 128 + (((k >> 3) ^ (n & 7)) << 4));
}

__global__ __launch_bounds__(256, 2)
void gemm1_mma_kernel() {
    extern __shared__ char smem[];
    uint32_t sb = smem_u32(smem);
    int tid  = threadIdx.x;
    int lane = tid & 31, wid = tid >> 5;
    int warp_m = wid & 1;        // 0..1 -> 32-row slab
    int warp_n = wid >> 1;       // 0..3 -> 32-col slab
    int nbase = blockIdx.x * 128;
    int mbase = blockIdx.y * 64;

    if (tid < 32)
        ((float4*)(smem + SM_BIAS))[tid] = ((const float4*)(g_bias + nbase))[tid];

    float acc[2][4][4];
#pragma unroll
    for (int i = 0; i < 2; i++)
#pragma unroll
        for (int j = 0; j < 4; j++)
#pragma unroll
            for (int q = 0; q < 4; q++) acc[i][j][q] = 0.f;

    uint32_t stg[2] = { sb + SM_STAGE0, sb + SM_STAGE0 + STAGE_BYTES };

    // prologue: stages 0 and 1 in flight
    load_stage(stg[0], mbase, nbase, 0, tid);
    CP_COMMIT();
    load_stage(stg[1], mbase, nbase, 64, tid);
    CP_COMMIT();

    for (int kt = 0; kt < 8; kt++) {
        int cur = kt & 1;
        if (kt < 7) CP_WAIT1(); else CP_WAIT0();
        __syncthreads();

        uint32_t sa0 = stg[cur] + STG_A0, sa1 = stg[cur] + STG_A1;
        uint32_t sb0 = stg[cur] + STG_B0, sb1 = stg[cur] + STG_B1;
#pragma unroll
        for (int ks = 0; ks < 4; ks++) {
            int k0 = ks * 16;
            uint32_t a[2][4], b[2][4];
            // pass 1: A0 * B0
#pragma unroll
            for (int mf = 0; mf < 2; mf++)
                ldsm_x4(a[mf], addrA(sa0, warp_m * 32 + mf * 16, k0, lane));
#pragma unroll
            for (int g = 0; g < 2; g++)
                ldsm_x4(b[g], addrB(sb0, warp_n * 32 + g * 16, k0, lane));
#pragma unroll
            for (int mf = 0; mf < 2; mf++)
#pragma unroll
                for (int nf = 0; nf < 4; nf++)
                    mma16816(acc[mf][nf], a[mf],
                             b[nf >> 1][(nf & 1) * 2], b[nf >> 1][(nf & 1) * 2 + 1]);
            // pass 2: A1 * B0
#pragma unroll
            for (int mf = 0; mf < 2; mf++)
                ldsm_x4(a[mf], addrA(sa1, warp_m * 32 + mf * 16, k0, lane));
#pragma unroll
            for (int mf = 0; mf < 2; mf++)
#pragma unroll
                for (int nf = 0; nf < 4; nf++)
                    mma16816(acc[mf][nf], a[mf],
                             b[nf >> 1][(nf & 1) * 2], b[nf >> 1][(nf & 1) * 2 + 1]);
            // pass 3: A0 * B1
#pragma unroll
            for (int mf = 0; mf < 2; mf++)
                ldsm_x4(a[mf], addrA(sa0, warp_m * 32 + mf * 16, k0, lane));
#pragma unroll
            for (int g = 0; g < 2; g++)
                ldsm_x4(b[g], addrB(sb1, warp_n * 32 + g * 16, k0, lane));
#pragma unroll
            for (int mf = 0; mf < 2; mf++)
#pragma unroll
                for (int nf = 0; nf < 4; nf++)
                    mma16816(acc[mf][nf], a[mf],
                             b[nf >> 1][(nf & 1) * 2], b[nf >> 1][(nf & 1) * 2 + 1]);
        }
        __syncthreads();
        if (kt + 2 < 8) {
            load_stage(stg[cur], mbase, nbase, (kt + 2) * 64, tid);
            CP_COMMIT();
        }
    }

    // epilogue
    const float* bs = (const float*)(smem + SM_BIAS);
#pragma unroll
    for (int mf = 0; mf < 2; mf++) {
#pragma unroll
        for (int nf = 0; nf < 4; nf++) {
            int ncol = warp_n * 32 + nf * 8 + (lane & 3) * 2;
            float bx = bs[ncol], by = bs[ncol + 1];
            int r0 = mbase + warp_m * 32 + mf * 16 + (lane >> 2);
            if (r0 < NN) {
                float2 v = make_float2(acc[mf][nf][0] + bx, acc[mf][nf][1] + by);
                *(float2*)(g_H0 + (size_t)r0 * HID2 + nbase + ncol) = v;
            }
            int r1 = r0 + 8;
            if (r1 < NN) {
                float2 v = make_float2(acc[mf][nf][2] + bx, acc[mf][nf][3] + by);
                *(float2*)(g_H0 + (size_t)r1 * HID2 + nbase + ncol) = v;
            }
        }
    }
}

// ---------------- SPMM1 + ReLU: H1[r] = relu(sum_e w * H0[col]) --------------
__global__ __launch_bounds__(128)
void spmm1_kernel() {
    int r = blockIdx.x;
    int t = threadIdx.x;
    const float4* H0 = (const float4*)g_H0;
    float4 acc = make_float4(0.f, 0.f, 0.f, 0.f);
    int beg = g_rowptr[r], end = g_rowptr[r + 1];
    int e = beg;
    for (; e + 3 < end; e += 4) {
        int c0 = __ldg(&g_cols[e]),     c1 = __ldg(&g_cols[e + 1]);
        int c2 = __ldg(&g_cols[e + 2]), c3 = __ldg(&g_cols[e + 3]);
        float w0 = __ldg(&g_w[e]),     w1 = __ldg(&g_w[e + 1]);
        float w2 = __ldg(&g_w[e + 2]), w3 = __ldg(&g_w[e + 3]);
        float4 v0 = H0[(size_t)c0 * 128 + t];
        float4 v1 = H0[(size_t)c1 * 128 + t];
        float4 v2 = H0[(size_t)c2 * 128 + t];
        float4 v3 = H0[(size_t)c3 * 128 + t];
        acc.x += w0 * v0.x + w1 * v1.x + w2 * v2.x + w3 * v3.x;
        acc.y += w0 * v0.y + w1 * v1.y + w2 * v2.y + w3 * v3.y;
        acc.z += w0 * v0.z + w1 * v1.z + w2 * v2.z + w3 * v3.z;
        acc.w += w0 * v0.w + w1 * v1.w + w2 * v2.w + w3 * v3.w;
    }
    for (; e < end; e++) {
        int c0 = __ldg(&g_cols[e]);
        float w0 = __ldg(&g_w[e]);
        float4 v0 = H0[(size_t)c0 * 128 + t];
        acc.x += w0 * v0.x; acc.y += w0 * v0.y;
        acc.z += w0 * v0.z; acc.w += w0 * v0.w;
    }
    acc.x = fmaxf(acc.x, 0.f); acc.y = fmaxf(acc.y, 0.f);
    acc.z = fmaxf(acc.z, 0.f); acc.w = fmaxf(acc.w, 0.f);
    ((float4*)g_H1)[(size_t)r * 128 + t] = acc;
}

// ---------------- GEMM2: H2[row][0:10]=H1a@W2_1+b, [10:20]=H1b@W2_2+b --------
__global__ __launch_bounds__(256)
void gemm2_kernel(const float* __restrict__ Wa, const float* __restrict__ ba,
                  const float* __restrict__ Wb, const float* __restrict__ bb) {
    __shared__ float Ws[2 * NH * NC];
    for (int i = threadIdx.x; i < NH * NC; i += 256) {
        Ws[i]           = Wa[i];
        Ws[NH * NC + i] = Wb[i];
    }
    __syncthreads();

    int i = blockIdx.x * blockDim.x + threadIdx.x;
    if (i >= NN * 2 * NC) return;
    int row = i / (2 * NC);
    int c   = i - row * (2 * NC);
    int net = c / NC;
    int cc  = c - net * NC;

    const float* W = Ws + net * NH * NC;
    const float4* h = (const float4*)(g_H1 + (size_t)row * HID2 + net * NH);
    float acc = net ? bb[cc] : ba[cc];
#pragma unroll 4
    for (int k4 = 0; k4 < NH / 4; k4++) {
        float4 v = h[k4];
        int kb = k4 * 4;
        acc += v.x * W[(kb + 0) * NC + cc];
        acc += v.y * W[(kb + 1) * NC + cc];
        acc += v.z * W[(kb + 2) * NC + cc];
        acc += v.w * W[(kb + 3) * NC + cc];
    }
    g_H2[i] = acc;
}

// ---------------- SPMM2 -> output: warp per row, 20 active lanes -------------
__global__ __launch_bounds__(256)
void spmm2_kernel(float* __restrict__ out) {
    int gid  = blockIdx.x * blockDim.x + threadIdx.x;
    int warp = gid >> 5;
    int lane = threadIdx.x & 31;
    if (warp >= NN) return;
    int beg = g_rowptr[warp], end = g_rowptr[warp + 1];
    float acc = 0.f;
    for (int e = beg; e < end; e++) {
        int c = __ldg(&g_cols[e]);
        float w = __ldg(&g_w[e]);
        if (lane < 2 * NC) acc += w * g_H2[(size_t)c * 2 * NC + lane];
    }
    if (lane < NC)
        out[(size_t)warp * NC + lane] = acc;
    else if (lane < 2 * NC)
        out[(size_t)NN * NC + (size_t)warp * NC + (lane - NC)] = acc;
}

// ---------------- launch -----------------------------------------------------
extern "C" void kernel_launch(void* const* d_in, const int* in_sizes, int n_in,
                              void* d_out, int out_size) {
    const float* x    = (const float*)d_in[0];
    const void*  ei   = d_in[1];
    const float* ew   = (const float*)d_in[2];
    const float* W1a  = (const float*)d_in[3];
    const float* b1a  = (const float*)d_in[4];
    const float* W2a  = (const float*)d_in[5];
    const float* b2a  = (const float*)d_in[6];
    const float* W1b  = (const float*)d_in[7];
    const float* b1b  = (const float*)d_in[8];
    const float* W2b  = (const float*)d_in[9];
    const float* b2b  = (const float*)d_in[10];
    float* out = (float*)d_out;

    cudaFuncSetAttribute(gemm1_mma_kernel,
                         cudaFuncAttributeMaxDynamicSharedMemorySize, GEMM1_SMEM);

    // CSR build (dtype-safe, graph-capturable)
    zero_kernel<<<(NN + 255) / 256, 256>>>();
    detect_kernel<<<(NE + 255) / 256, 256>>>((const long long*)ei);
    count_kernel<<<(NE + 255) / 256, 256>>>(ei);
    scan1_kernel<<<SCAN_NB, 256>>>();
    scan2_kernel<<<1, 256>>>();
    scan3_kernel<<<(NN + 255) / 256, 256>>>();
    scatter_kernel<<<(NE + 255) / 256, 256>>>(ei, ew);

    // bf16x2 split conversions
    convertA_kernel<<<(NN * (KPAD / 2) + 255) / 256, 256>>>(x);
    convertB_kernel<<<(HID2 * (KPAD / 2) + 255) / 256, 256>>>(W1a, b1a, W1b, b1b);

    // layer 1 linear on tensor cores (mma.sync bf16 split, 2-stage pipeline)
    dim3 g1(HID2 / 128, (NN + 63) / 64);
    gemm1_mma_kernel<<<g1, 256, GEMM1_SMEM>>>();

    // propagate + relu
    spmm1_kernel<<<NN, 128>>>();

    // layer 2 linear
    gemm2_kernel<<<(NN * 2 * NC + 255) / 256, 256>>>(W2a, b2a, W2b, b2b);

    // propagate -> outputs
    spmm2_kernel<<<(NN * 32 + 255) / 256, 256>>>(out);
}

// round 8
// speedup vs baseline: 1.5312x; 1.0432x over previous
#include <cuda_runtime.h>
#include <cuda_bf16.h>
#include <cstdint>

#define NN 50000
#define NE 800000
#define NF 500
#define NH 256
#define NC 10
#define HID2 512   // both networks' hidden concatenated
#define KPAD 512   // padded K for tensor-core GEMM

// ---------------- scratch (device globals; no runtime allocation) -----------
__device__ __align__(256) float g_H0[NN * HID2];   // x@W1 + b1 (both nets)
__device__ __align__(256) float g_H2[NN * 2 * NC]; // spmm+relu -> @W2 + b2
__device__ __align__(256) __nv_bfloat16 g_A0[NN * KPAD];   // hi(x), K-padded
__device__ __align__(256) __nv_bfloat16 g_A1[NN * KPAD];   // lo(x)
__device__ __align__(256) __nv_bfloat16 g_B0[HID2 * KPAD]; // hi(W^T) [n][k]
__device__ __align__(256) __nv_bfloat16 g_B1[HID2 * KPAD]; // lo(W^T)
__device__ __align__(256) float g_bias[HID2];
__device__ int   g_rowptr[NN + 1];
__device__ int   g_cnt[NN];
__device__ int   g_fill[NN];
__device__ int   g_btot[256];
__device__ int   g_cols[NE];
__device__ float g_w[NE];
__device__ int   g_is64;

// ================= helpers ===================================================
__device__ __forceinline__ uint32_t smem_u32(const void* p) {
    uint32_t a;
    asm("{ .reg .u64 t; cvta.to.shared.u64 t, %1; cvt.u32.u64 %0, t; }"
        : "=r"(a) : "l"(p));
    return a;
}
#define SMEM_SWIZZLE_128B(off) ((off) ^ (((off) >> 3) & 0x70))

__device__ __forceinline__ void ldsm_x4(uint32_t* d, uint32_t addr) {
    asm volatile("ldmatrix.sync.aligned.m8n8.x4.shared.b16 {%0,%1,%2,%3}, [%4];"
                 : "=r"(d[0]), "=r"(d[1]), "=r"(d[2]), "=r"(d[3]) : "r"(addr));
}
__device__ __forceinline__ void mma16816(float* c, const uint32_t* a,
                                         uint32_t b0, uint32_t b1) {
    asm volatile("mma.sync.aligned.m16n8k16.row.col.f32.bf16.bf16.f32 "
                 "{%0,%1,%2,%3}, {%4,%5,%6,%7}, {%8,%9}, {%0,%1,%2,%3};"
                 : "+f"(c[0]), "+f"(c[1]), "+f"(c[2]), "+f"(c[3])
                 : "r"(a[0]), "r"(a[1]), "r"(a[2]), "r"(a[3]), "r"(b0), "r"(b1));
}
__device__ __forceinline__ void cp_async16(uint32_t dst, const void* src, int src_sz) {
    asm volatile("cp.async.cg.shared.global [%0], [%1], 16, %2;"
                 :: "r"(dst), "l"(src), "r"(src_sz) : "memory");
}
#define CP_COMMIT() asm volatile("cp.async.commit_group;" ::: "memory")
#define CP_WAIT1()  asm volatile("cp.async.wait_group 1;" ::: "memory")
#define CP_WAIT0()  asm volatile("cp.async.wait_group 0;" ::: "memory")

// ---------------- dtype detect + CSR build ----------------------------------
__global__ void zero_kernel() {
    int i = blockIdx.x * blockDim.x + threadIdx.x;
    if (i < NN) { g_cnt[i] = 0; g_fill[i] = 0; }
    if (i == 0) g_is64 = 1;
}

__global__ void detect_kernel(const long long* __restrict__ ei) {
    int e = blockIdx.x * blockDim.x + threadIdx.x;
    if (e < NE) {
        long long v = ei[e];
        if (v < 0 || v >= NN) atomicAnd(&g_is64, 0);
    }
}

__device__ __forceinline__ int edge_row(const void* ei, int e) {
    return g_is64 ? (int)((const long long*)ei)[e] : ((const int*)ei)[e];
}
__device__ __forceinline__ int edge_col(const void* ei, int e) {
    return g_is64 ? (int)((const long long*)ei)[NE + e] : ((const int*)ei)[NE + e];
}

__global__ void count_kernel(const void* __restrict__ ei) {
    int e = blockIdx.x * blockDim.x + threadIdx.x;
    if (e < NE) atomicAdd(&g_cnt[edge_row(ei, e)], 1);
}

// 3-phase parallel scan
#define SCAN_NB ((NN + 255) / 256)   // 196
__global__ void scan1_kernel() {
    __shared__ int sh[256];
    int t = threadIdx.x, b = blockIdx.x;
    int i = b * 256 + t;
    int v = (i < NN) ? g_cnt[i] : 0;
    sh[t] = v; __syncthreads();
    for (int off = 1; off < 256; off <<= 1) {
        int u = (t >= off) ? sh[t - off] : 0;
        __syncthreads(); sh[t] += u; __syncthreads();
    }
    if (i < NN) g_rowptr[i] = sh[t] - v;
    if (t == 255) g_btot[b] = sh[255];
}
__global__ void scan2_kernel() {
    __shared__ int sh[256];
    int t = threadIdx.x;
    int v = (t < SCAN_NB) ? g_btot[t] : 0;
    sh[t] = v; __syncthreads();
    for (int off = 1; off < 256; off <<= 1) {
        int u = (t >= off) ? sh[t - off] : 0;
        __syncthreads(); sh[t] += u; __syncthreads();
    }
    if (t < SCAN_NB) g_btot[t] = sh[t] - v;
    if (t == SCAN_NB - 1) g_rowptr[NN] = sh[t];
}
__global__ void scan3_kernel() {
    int i = blockIdx.x * blockDim.x + threadIdx.x;
    if (i < NN) g_rowptr[i] += g_btot[i >> 8];
}

__global__ void scatter_kernel(const void* __restrict__ ei,
                               const float* __restrict__ ew) {
    int e = blockIdx.x * blockDim.x + threadIdx.x;
    if (e < NE) {
        int r = edge_row(ei, e);
        int c = edge_col(ei, e);
        int pos = g_rowptr[r] + atomicAdd(&g_fill[r], 1);
        g_cols[pos] = c;
        g_w[pos]    = ew[e];
    }
}

// ---------------- bf16x2 split conversions -----------------------------------
__device__ __forceinline__ uint32_t split_pack_hi(float a, float b,
                                                  float& ra, float& rb) {
    __nv_bfloat16 ha = __float2bfloat16_rn(a);
    __nv_bfloat16 hb = __float2bfloat16_rn(b);
    ra = a - __bfloat162float(ha);
    rb = b - __bfloat162float(hb);
    return (uint32_t)__bfloat16_as_ushort(ha) |
           ((uint32_t)__bfloat16_as_ushort(hb) << 16);
}
__device__ __forceinline__ uint32_t pack_bf16(float a, float b) {
    return (uint32_t)__bfloat16_as_ushort(__float2bfloat16_rn(a)) |
           ((uint32_t)__bfloat16_as_ushort(__float2bfloat16_rn(b)) << 16);
}

__global__ void convertA_kernel(const float* __restrict__ x) {
    int idx = blockIdx.x * blockDim.x + threadIdx.x;   // row*256 + k2
    if (idx >= NN * (KPAD / 2)) return;
    int row = idx >> 8;
    int k2  = idx & 255;
    float2 v = make_float2(0.f, 0.f);
    if (k2 < NF / 2)
        v = *(const float2*)(x + (size_t)row * NF + 2 * k2);
    float ra, rb;
    uint32_t hi = split_pack_hi(v.x, v.y, ra, rb);
    ((uint32_t*)g_A0)[idx] = hi;
    ((uint32_t*)g_A1)[idx] = pack_bf16(ra, rb);
}

__global__ void convertB_kernel(const float* __restrict__ Wa, const float* __restrict__ ba,
                                const float* __restrict__ Wb, const float* __restrict__ bb) {
    int idx = blockIdx.x * blockDim.x + threadIdx.x;   // n*256 + k2
    if (idx >= HID2 * (KPAD / 2)) return;
    int n  = idx >> 8;
    int k2 = idx & 255;
    int net = n >> 8;
    int col = n & (NH - 1);
    const float* W = net ? Wb : Wa;
    int k = 2 * k2;
    float a = (k     < NF) ? W[(size_t)k       * NH + col] : 0.f;
    float b = (k + 1 < NF) ? W[(size_t)(k + 1) * NH + col] : 0.f;
    float ra, rb;
    uint32_t hi = split_pack_hi(a, b, ra, rb);
    ((uint32_t*)g_B0)[idx] = hi;
    ((uint32_t*)g_B1)[idx] = pack_bf16(ra, rb);
    if (k2 == 0) g_bias[n] = net ? bb[col] : ba[col];
}

// ---------------- GEMM1 (mma.sync, cp.async 2-stage): H0 = A@B^T + bias ------
// CTA tile M=64, N=128, BK=64. 8 warps (2m x 4n), warp tile 32x32.
#define SM_BIAS   0
#define SM_STAGE0 1024
#define STG_A0    0
#define STG_A1    8192
#define STG_B0    16384
#define STG_B1    32768
#define STAGE_BYTES 49152
#define GEMM1_SMEM (SM_STAGE0 + 2 * STAGE_BYTES)   // 99328 bytes

__device__ __forceinline__ void load_stage(uint32_t stage_base, int mbase, int nbase,
                                           int k0, int tid) {
#pragma unroll
    for (int p = 0; p < 2; p++) {
        uint32_t off = (uint32_t)(tid + p * 256) * 16;   // 0..8176
        int row = off >> 7, inner = off & 127;
        int grow = mbase + row;
        int ok = (grow < NN) ? 16 : 0;
        int gr = (grow < NN) ? grow : (NN - 1);
        uint32_t sw = SMEM_SWIZZLE_128B(off);
        cp_async16(stage_base + STG_A0 + sw,
                   (const char*)g_A0 + ((size_t)gr * KPAD + k0) * 2 + inner, ok);
        cp_async16(stage_base + STG_A1 + sw,
                   (const char*)g_A1 + ((size_t)gr * KPAD + k0) * 2 + inner, ok);
    }
#pragma unroll
    for (int p = 0; p < 4; p++) {
        uint32_t off = (uint32_t)(tid + p * 256) * 16;   // 0..16368
        int row = off >> 7, inner = off & 127;
        int nrow = nbase + row;
        uint32_t sw = SMEM_SWIZZLE_128B(off);
        cp_async16(stage_base + STG_B0 + sw,
                   (const char*)g_B0 + ((size_t)nrow * KPAD + k0) * 2 + inner, 16);
        cp_async16(stage_base + STG_B1 + sw,
                   (const char*)g_B1 + ((size_t)nrow * KPAD + k0) * 2 + inner, 16);
    }
}

__device__ __forceinline__ uint32_t addrA(uint32_t base, int m_local, int k0, int lane) {
    int mat = lane >> 3, r = lane & 7;
    int m = m_local + r + (mat & 1) * 8;
    int k = k0 + (mat >> 1) * 8;
    return base + (uint32_t)(m * 128 + (((k >> 3) ^ (m & 7)) << 4));
}
__device__ __forceinline__ uint32_t addrB(uint32_t base, int n_local, int k0, int lane) {
    int mat = lane >> 3, r = lane & 7;
    int n = n_local + r + ((mat >> 1) & 1) * 8;
    int k = k0 + (mat & 1) * 8;
    return base + (uint32_t)(n * 128 + (((k >> 3) ^ (n & 7)) << 4));
}

__global__ __launch_bounds__(256, 2)
void gemm1_mma_kernel() {
    extern __shared__ char smem[];
    uint32_t sb = smem_u32(smem);
    int tid  = threadIdx.x;
    int lane = tid & 31, wid = tid >> 5;
    int warp_m = wid & 1;
    int warp_n = wid >> 1;
    int nbase = blockIdx.x * 128;
    int mbase = blockIdx.y * 64;

    if (tid < 32)
        ((float4*)(smem + SM_BIAS))[tid] = ((const float4*)(g_bias + nbase))[tid];

    float acc[2][4][4];
#pragma unroll
    for (int i = 0; i < 2; i++)
#pragma unroll
        for (int j = 0; j < 4; j++)
#pragma unroll
            for (int q = 0; q < 4; q++) acc[i][j][q] = 0.f;

    uint32_t stg[2] = { sb + SM_STAGE0, sb + SM_STAGE0 + STAGE_BYTES };

    load_stage(stg[0], mbase, nbase, 0, tid);
    CP_COMMIT();
    load_stage(stg[1], mbase, nbase, 64, tid);
    CP_COMMIT();

    for (int kt = 0; kt < 8; kt++) {
        int cur = kt & 1;
        if (kt < 7) CP_WAIT1(); else CP_WAIT0();
        __syncthreads();

        uint32_t sa0 = stg[cur] + STG_A0, sa1 = stg[cur] + STG_A1;
        uint32_t sb0 = stg[cur] + STG_B0, sb1 = stg[cur] + STG_B1;
#pragma unroll
        for (int ks = 0; ks < 4; ks++) {
            int k0 = ks * 16;
            uint32_t a[2][4], b[2][4];
#pragma unroll
            for (int mf = 0; mf < 2; mf++)
                ldsm_x4(a[mf], addrA(sa0, warp_m * 32 + mf * 16, k0, lane));
#pragma unroll
            for (int g = 0; g < 2; g++)
                ldsm_x4(b[g], addrB(sb0, warp_n * 32 + g * 16, k0, lane));
#pragma unroll
            for (int mf = 0; mf < 2; mf++)
#pragma unroll
                for (int nf = 0; nf < 4; nf++)
                    mma16816(acc[mf][nf], a[mf],
                             b[nf >> 1][(nf & 1) * 2], b[nf >> 1][(nf & 1) * 2 + 1]);
#pragma unroll
            for (int mf = 0; mf < 2; mf++)
                ldsm_x4(a[mf], addrA(sa1, warp_m * 32 + mf * 16, k0, lane));
#pragma unroll
            for (int mf = 0; mf < 2; mf++)
#pragma unroll
                for (int nf = 0; nf < 4; nf++)
                    mma16816(acc[mf][nf], a[mf],
                             b[nf >> 1][(nf & 1) * 2], b[nf >> 1][(nf & 1) * 2 + 1]);
#pragma unroll
            for (int mf = 0; mf < 2; mf++)
                ldsm_x4(a[mf], addrA(sa0, warp_m * 32 + mf * 16, k0, lane));
#pragma unroll
            for (int g = 0; g < 2; g++)
                ldsm_x4(b[g], addrB(sb1, warp_n * 32 + g * 16, k0, lane));
#pragma unroll
            for (int mf = 0; mf < 2; mf++)
#pragma unroll
                for (int nf = 0; nf < 4; nf++)
                    mma16816(acc[mf][nf], a[mf],
                             b[nf >> 1][(nf & 1) * 2], b[nf >> 1][(nf & 1) * 2 + 1]);
        }
        __syncthreads();
        if (kt + 2 < 8) {
            load_stage(stg[cur], mbase, nbase, (kt + 2) * 64, tid);
            CP_COMMIT();
        }
    }

    const float* bs = (const float*)(smem + SM_BIAS);
#pragma unroll
    for (int mf = 0; mf < 2; mf++) {
#pragma unroll
        for (int nf = 0; nf < 4; nf++) {
            int ncol = warp_n * 32 + nf * 8 + (lane & 3) * 2;
            float bx = bs[ncol], by = bs[ncol + 1];
            int r0 = mbase + warp_m * 32 + mf * 16 + (lane >> 2);
            if (r0 < NN) {
                float2 v = make_float2(acc[mf][nf][0] + bx, acc[mf][nf][1] + by);
                *(float2*)(g_H0 + (size_t)r0 * HID2 + nbase + ncol) = v;
            }
            int r1 = r0 + 8;
            if (r1 < NN) {
                float2 v = make_float2(acc[mf][nf][2] + bx, acc[mf][nf][3] + by);
                *(float2*)(g_H0 + (size_t)r1 * HID2 + nbase + ncol) = v;
            }
        }
    }
}

// ---------------- SPMM1 + ReLU + GEMM2 fused ---------------------------------
// block per row: gather -> relu h1 row in smem -> 20-col dense layer -> g_H2
__global__ __launch_bounds__(128)
void spmm1_fused_kernel(const float* __restrict__ W2a, const float* __restrict__ b2a,
                        const float* __restrict__ W2b, const float* __restrict__ b2b) {
    __shared__ __align__(16) float sh[HID2];
    int r = blockIdx.x;
    int t = threadIdx.x;
    const float4* H0 = (const float4*)g_H0;
    float4 acc = make_float4(0.f, 0.f, 0.f, 0.f);
    int beg = g_rowptr[r], end = g_rowptr[r + 1];
    int e = beg;
    for (; e + 3 < end; e += 4) {
        int c0 = __ldg(&g_cols[e]),     c1 = __ldg(&g_cols[e + 1]);
        int c2 = __ldg(&g_cols[e + 2]), c3 = __ldg(&g_cols[e + 3]);
        float w0 = __ldg(&g_w[e]),     w1 = __ldg(&g_w[e + 1]);
        float w2 = __ldg(&g_w[e + 2]), w3 = __ldg(&g_w[e + 3]);
        float4 v0 = H0[(size_t)c0 * 128 + t];
        float4 v1 = H0[(size_t)c1 * 128 + t];
        float4 v2 = H0[(size_t)c2 * 128 + t];
        float4 v3 = H0[(size_t)c3 * 128 + t];
        acc.x += w0 * v0.x + w1 * v1.x + w2 * v2.x + w3 * v3.x;
        acc.y += w0 * v0.y + w1 * v1.y + w2 * v2.y + w3 * v3.y;
        acc.z += w0 * v0.z + w1 * v1.z + w2 * v2.z + w3 * v3.z;
        acc.w += w0 * v0.w + w1 * v1.w + w2 * v2.w + w3 * v3.w;
    }
    for (; e < end; e++) {
        int c0 = __ldg(&g_cols[e]);
        float w0 = __ldg(&g_w[e]);
        float4 v0 = H0[(size_t)c0 * 128 + t];
        acc.x += w0 * v0.x; acc.y += w0 * v0.y;
        acc.z += w0 * v0.z; acc.w += w0 * v0.w;
    }
    acc.x = fmaxf(acc.x, 0.f); acc.y = fmaxf(acc.y, 0.f);
    acc.z = fmaxf(acc.z, 0.f); acc.w = fmaxf(acc.w, 0.f);
    ((float4*)sh)[t] = acc;
    __syncthreads();

    // dense layer: 20 outputs over 4 warps (5 each)
    int warp = t >> 5, lane = t & 31;
#pragma unroll
    for (int j = 0; j < 5; j++) {
        int c   = warp * 5 + j;          // 0..19
        int net = (c >= NC) ? 1 : 0;
        int cc  = c - net * NC;
        const float* W = net ? W2b : W2a;
        const float* h = sh + net * NH;
        float s = 0.f;
#pragma unroll
        for (int i = 0; i < NH / 32; i++) {
            int k = lane + i * 32;
            s += h[k] * __ldg(&W[(size_t)k * NC + cc]);
        }
#pragma unroll
        for (int o = 16; o; o >>= 1) s += __shfl_xor_sync(0xFFFFFFFFu, s, o);
        if (lane == 0)
            g_H2[(size_t)r * 2 * NC + c] =
                s + (net ? __ldg(&b2b[cc]) : __ldg(&b2a[cc]));
    }
}

// ---------------- SPMM2 -> output: warp per row, 20 active lanes -------------
__global__ __launch_bounds__(256)
void spmm2_kernel(float* __restrict__ out) {
    int gid  = blockIdx.x * blockDim.x + threadIdx.x;
    int warp = gid >> 5;
    int lane = threadIdx.x & 31;
    if (warp >= NN) return;
    int beg = g_rowptr[warp], end = g_rowptr[warp + 1];
    float acc = 0.f;
    for (int e = beg; e < end; e++) {
        int c = __ldg(&g_cols[e]);
        float w = __ldg(&g_w[e]);
        if (lane < 2 * NC) acc += w * g_H2[(size_t)c * 2 * NC + lane];
    }
    if (lane < NC)
        out[(size_t)warp * NC + lane] = acc;
    else if (lane < 2 * NC)
        out[(size_t)NN * NC + (size_t)warp * NC + (lane - NC)] = acc;
}

// ---------------- launch -----------------------------------------------------
extern "C" void kernel_launch(void* const* d_in, const int* in_sizes, int n_in,
                              void* d_out, int out_size) {
    const float* x    = (const float*)d_in[0];
    const void*  ei   = d_in[1];
    const float* ew   = (const float*)d_in[2];
    const float* W1a  = (const float*)d_in[3];
    const float* b1a  = (const float*)d_in[4];
    const float* W2a  = (const float*)d_in[5];
    const float* b2a  = (const float*)d_in[6];
    const float* W1b  = (const float*)d_in[7];
    const float* b1b  = (const float*)d_in[8];
    const float* W2b  = (const float*)d_in[9];
    const float* b2b  = (const float*)d_in[10];
    float* out = (float*)d_out;

    cudaFuncSetAttribute(gemm1_mma_kernel,
                         cudaFuncAttributeMaxDynamicSharedMemorySize, GEMM1_SMEM);

    // CSR build (dtype-safe, graph-capturable)
    zero_kernel<<<(NN + 255) / 256, 256>>>();
    detect_kernel<<<(NE + 255) / 256, 256>>>((const long long*)ei);
    count_kernel<<<(NE + 255) / 256, 256>>>(ei);
    scan1_kernel<<<SCAN_NB, 256>>>();
    scan2_kernel<<<1, 256>>>();
    scan3_kernel<<<(NN + 255) / 256, 256>>>();
    scatter_kernel<<<(NE + 255) / 256, 256>>>(ei, ew);

    // bf16x2 split conversions
    convertA_kernel<<<(NN * (KPAD / 2) + 255) / 256, 256>>>(x);
    convertB_kernel<<<(HID2 * (KPAD / 2) + 255) / 256, 256>>>(W1a, b1a, W1b, b1b);

    // layer 1 linear on tensor cores (mma.sync bf16 split, 2-stage pipeline)
    dim3 g1(HID2 / 128, (NN + 63) / 64);
    gemm1_mma_kernel<<<g1, 256, GEMM1_SMEM>>>();

    // propagate + relu + layer-2 linear (fused)
    spmm1_fused_kernel<<<NN, 128>>>(W2a, b2a, W2b, b2b);

    // propagate -> outputs
    spmm2_kernel<<<(NN * 32 + 255) / 256, 256>>>(out);
}